// round 13
// baseline (speedup 1.0000x reference)
#include <cuda_runtime.h>

// Problem constants (from reference setup_inputs)
#define NB 8
#define NC 64
#define HH 128
#define WW 128
#define EH 64
#define EW 64
#define THETA 10.0f

#define CSPW 16                        // channels per warp
#define NCGRP 4                        // channel groups per block
#define ROWS_PER_BLK 2                 // rows per block
#define NROWBLK (HH / ROWS_PER_BLK)    // 64
#define NWARP 8                        // 2 rows x 4 cgroups
#define TBLK (NWARP * 32)              // 256 threads
#define NSTAGE 3                       // cp.async ring depth (2 ahead)

#define CP16(dst, src) \
    asm volatile("cp.async.cg.shared.global [%0], [%1], 16;" \
                 :: "r"(dst), "l"(src) : "memory")
#define CPCOMMIT() asm volatile("cp.async.commit_group;" ::: "memory")
#define CPWAIT2()  asm volatile("cp.async.wait_group 2;"  ::: "memory")

// ---------------------------------------------------------------------------
// Fully fused: one block = 2 output rows x 4 channel-groups (8 warps).
// Warps 0-1 compute the per-pixel softmax weights for the block's 2 rows ONCE
// (boundary zero-padding folded into the weights) and publish via smem; after
// a single __syncthreads, every warp runs a warp-private cp.async channel
// pipeline (2 channels ahead, per-warp commit/wait, no further barriers).
// ---------------------------------------------------------------------------
__global__ __launch_bounds__(TBLK, 4)
void geg_fused_kernel(const float* __restrict__ mask,
                      const float* __restrict__ edge,
                      float* __restrict__ out)
{
    __shared__ float4 sbuf[NWARP][NSTAGE][3][32];   // 36 KB staging
    __shared__ float  wsh[ROWS_PER_BLK][9][WW];     // 9 KB shared weights

    const int t    = threadIdx.x;
    const int warp = t >> 5;
    const int lane = t & 31;
    const int rowwarp = warp & 1;      // row within block
    const int cgrp    = warp >> 1;     // channel group 0..3

    const int rowblk = blockIdx.x;     // 0..63
    const int n      = blockIdx.y;     // 0..7

    const int y  = rowblk * ROWS_PER_BLK + rowwarp;  // output row
    const int x0 = lane * 4;

    const int img  = HH * WW;
    const int base = (n * NC + cgrp * CSPW) * img;
    const float* mp = mask + base;
    float*       op = out  + base;

    // Clamped row offsets (OOB rows carry zero weight).
    const int off0 = max(y - 1, 0)      * WW + x0;
    const int off1 = y                  * WW + x0;
    const int off2 = min(y + 1, HH - 1) * WW + x0;
    const int offs = y * WW + x0;

    const unsigned sbase =
        (unsigned)__cvta_generic_to_shared(&sbuf[warp][0][0][lane]);
    // stage stride = 1536 B; row stride = 512 B

    // ---- cp.async prologue: channels 0..1 in flight -----------------------
    {
        const float* p0 = mp;
        CP16(sbase,        p0 + off0);
        CP16(sbase + 512,  p0 + off1);
        CP16(sbase + 1024, p0 + off2);
        CPCOMMIT();
        const float* p1 = mp + img;
        CP16(sbase + 1536,        p1 + off0);
        CP16(sbase + 1536 + 512,  p1 + off1);
        CP16(sbase + 1536 + 1024, p1 + off2);
        CPCOMMIT();
    }

    // ---- weights: computed ONCE per row by warps 0-1, shared via smem -----
    if (warp < 2) {
        const float* eptr = edge + n * (EH * EW);
        const float sc = 63.0f / 127.0f;   // (EH-1)/(HH-1), align_corners

        // e_up(y+dy, x0-1 .. x0+4); zero outside image (reference pads AFTER
        // upsampling). Horizontal neighbors via warp shuffle.
        float er[3][6];
        #pragma unroll
        for (int r = 0; r < 3; r++) {
            const int gy = y - 1 + r;
            float4 ev = make_float4(0.f, 0.f, 0.f, 0.f);
            if (gy >= 0 && gy < HH) {
                const float ys = (float)gy * sc;
                const int   yi = (int)ys;
                const float wy = ys - (float)yi;
                const int   y1 = min(yi + 1, EH - 1);
                const float* r0 = eptr + yi * EW;
                const float* r1 = eptr + y1 * EW;
                float v[4];
                #pragma unroll
                for (int p = 0; p < 4; p++) {
                    const int   gx = x0 + p;
                    const float xs = (float)gx * sc;
                    const int   xi = (int)xs;
                    const float wx = xs - (float)xi;
                    const int   x1 = min(xi + 1, EW - 1);
                    const float a  = r0[xi];
                    const float b  = r0[x1];
                    const float c0 = r1[xi];
                    const float d  = r1[x1];
                    const float top = a  + (b  - a ) * wx;
                    const float bot = c0 + (d  - c0) * wx;
                    v[p] = top + (bot - top) * wy;
                }
                ev = make_float4(v[0], v[1], v[2], v[3]);
            }
            float left  = __shfl_up_sync(0xffffffffu, ev.w, 1);
            float right = __shfl_down_sync(0xffffffffu, ev.x, 1);
            if (lane == 0)  left  = 0.f;
            if (lane == 31) right = 0.f;
            er[r][0] = left; er[r][1] = ev.x; er[r][2] = ev.y;
            er[r][3] = ev.z; er[r][4] = ev.w; er[r][5] = right;
        }

        float wtmp[4][9];
        #pragma unroll
        for (int p = 0; p < 4; p++) {
            const float ec = er[1][p + 1];
            float s = 0.f;
            #pragma unroll
            for (int k = 0; k < 9; k++) {
                const float d  = ec - er[k / 3][p + (k % 3)];
                const float pw = __expf(-THETA * d * d);
                wtmp[p][k] = pw;
                s += pw;
            }
            const float rs = 1.f / s;
            #pragma unroll
            for (int k = 0; k < 9; k++) wtmp[p][k] *= rs;
        }

        // Fold mask zero-padding into the (normalized) weights: a padded tap
        // contributes m=0, identical to zeroing its weight; the softmax
        // denominator already includes all 9 exps.
        if (y == 0) {
            #pragma unroll
            for (int p = 0; p < 4; p++) { wtmp[p][0] = 0.f; wtmp[p][1] = 0.f; wtmp[p][2] = 0.f; }
        }
        if (y == HH - 1) {
            #pragma unroll
            for (int p = 0; p < 4; p++) { wtmp[p][6] = 0.f; wtmp[p][7] = 0.f; wtmp[p][8] = 0.f; }
        }
        if (lane == 0)  { wtmp[0][0] = 0.f; wtmp[0][3] = 0.f; wtmp[0][6] = 0.f; }
        if (lane == 31) { wtmp[3][2] = 0.f; wtmp[3][5] = 0.f; wtmp[3][8] = 0.f; }

        #pragma unroll
        for (int k = 0; k < 9; k++)
            *reinterpret_cast<float4*>(&wsh[rowwarp][k][x0]) =
                make_float4(wtmp[0][k], wtmp[1][k], wtmp[2][k], wtmp[3][k]);
    }

    __syncthreads();   // once per block — weights published

    // Every warp loads its row's 36 weights from smem.
    float w[4][9];
    #pragma unroll
    for (int k = 0; k < 9; k++) {
        float4 v = *reinterpret_cast<const float4*>(&wsh[rowwarp][k][x0]);
        w[0][k] = v.x; w[1][k] = v.y; w[2][k] = v.z; w[3][k] = v.w;
    }

    // ---- channel loop: warp-private pipeline, no barriers ------------------
    const float4* stp0 = &sbuf[warp][0][0][lane];
    int cidx = 0;          // consume stage offset in float4 units (0,96,192)
    int poff = 3072;       // issue stage byte offset for channel c+2

    #pragma unroll 1
    for (int c = 0; c < CSPW; c++) {
        // Issue channel c+2. Empty commit groups in the tail keep wait_group
        // accounting sound.
        if (c + 2 < CSPW) {
            const float* p = mp + (c + 2) * img;
            CP16(sbase + poff,        p + off0);
            CP16(sbase + poff + 512,  p + off1);
            CP16(sbase + poff + 1024, p + off2);
        }
        CPCOMMIT();
        CPWAIT2();          // channel c's group is complete

        float4 m0 = stp0[cidx];
        float4 m1 = stp0[cidx + 32];
        float4 m2 = stp0[cidx + 64];

        float mr[3][6];
        {
            float l0 = __shfl_up_sync(0xffffffffu, m0.w, 1);
            float r0 = __shfl_down_sync(0xffffffffu, m0.x, 1);
            float l1 = __shfl_up_sync(0xffffffffu, m1.w, 1);
            float r1 = __shfl_down_sync(0xffffffffu, m1.x, 1);
            float l2 = __shfl_up_sync(0xffffffffu, m2.w, 1);
            float r2 = __shfl_down_sync(0xffffffffu, m2.x, 1);
            mr[0][0]=l0; mr[0][1]=m0.x; mr[0][2]=m0.y; mr[0][3]=m0.z; mr[0][4]=m0.w; mr[0][5]=r0;
            mr[1][0]=l1; mr[1][1]=m1.x; mr[1][2]=m1.y; mr[1][3]=m1.z; mr[1][4]=m1.w; mr[1][5]=r1;
            mr[2][0]=l2; mr[2][1]=m2.x; mr[2][2]=m2.y; mr[2][3]=m2.z; mr[2][4]=m2.w; mr[2][5]=r2;
        }

        float a[4];
        #pragma unroll
        for (int p = 0; p < 4; p++) {
            float s = 0.f;
            #pragma unroll
            for (int k = 0; k < 9; k++)
                s = fmaf(w[p][k], mr[k / 3][p + (k % 3)], s);
            a[p] = s;
        }

        *reinterpret_cast<float4*>(op + offs) = make_float4(a[0], a[1], a[2], a[3]);
        op += img;

        cidx = (cidx == 192) ? 0 : cidx + 96;
        poff = (poff == 3072) ? 0 : poff + 1536;
    }
}

extern "C" void kernel_launch(void* const* d_in, const int* in_sizes, int n_in,
                              void* d_out, int out_size)
{
    const float* mask = (const float*)d_in[0];
    const float* edge = (const float*)d_in[1];
    if (n_in >= 2 && in_sizes[0] < in_sizes[1]) {   // defensive swap by size
        const float* tmp = mask; mask = edge; edge = tmp;
    }
    float* out = (float*)d_out;

    dim3 grid(NROWBLK, NB);             // 64 x 8 = 512 blocks
    geg_fused_kernel<<<grid, TBLK>>>(mask, edge, out);
}

// round 14
// speedup vs baseline: 1.1165x; 1.1165x over previous
#include <cuda_runtime.h>

// Problem constants (from reference setup_inputs)
#define NB 8
#define NC 64
#define HH 128
#define WW 128
#define EH 64
#define EW 64
#define THETA 10.0f

#define CSPB 16                        // channels per block
#define NCGRP (NC / CSPB)              // 4 channel groups
#define ROWS_PER_BLK 4                 // 4 warps -> 4 rows
#define NROWBLK (HH / ROWS_PER_BLK)    // 32
#define TBLK (ROWS_PER_BLK * 32)       // 128 threads
#define NSTAGE 4                       // cp.async ring depth (3 ahead)

#define CP16(dst, src) \
    asm volatile("cp.async.cg.shared.global [%0], [%1], 16;" \
                 :: "r"(dst), "l"(src) : "memory")
#define CPCOMMIT() asm volatile("cp.async.commit_group;" ::: "memory")
#define CPWAIT3()  asm volatile("cp.async.wait_group 3;"  ::: "memory")

// ---------------------------------------------------------------------------
// Fused kernel (R12 structure): per-block weight computation (bilinear edge
// upsample + softmax, boundary padding folded into weights) followed by a
// FULLY UNROLLED 16-channel apply loop fed by a warp-private cp.async
// pipeline (3 channels ahead, per-warp commit/wait, no block barriers).
// Full unroll makes every stage/store/prefetch offset an immediate and
// resolves tail predication at compile time.
// ---------------------------------------------------------------------------
__global__ __launch_bounds__(TBLK, 7)
void geg_fused_kernel(const float* __restrict__ mask,
                      const float* __restrict__ edge,
                      float* __restrict__ out)
{
    // [warp][stage][row][lane] float4 = 24 KB
    __shared__ float4 sbuf[ROWS_PER_BLK][NSTAGE][3][32];

    const int t    = threadIdx.x;
    const int warp = t >> 5;
    const int lane = t & 31;

    const int rowblk = blockIdx.x;     // 0..31
    const int cgrp   = blockIdx.y;     // 0..3
    const int n      = blockIdx.z;     // 0..7

    const int y  = rowblk * ROWS_PER_BLK + warp;  // output row, 0..127
    const int x0 = lane * 4;

    const int img  = HH * WW;
    const int base = (n * NC + cgrp * CSPB) * img;

    // Clamped row offsets (OOB rows carry zero weight).
    const int off0 = max(y - 1, 0)      * WW + x0;
    const int off1 = y                  * WW + x0;
    const int off2 = min(y + 1, HH - 1) * WW + x0;

    // Per-warp base pointers; all channel offsets become immediates below.
    const float* p0 = mask + base + off0;
    const float* p1 = mask + base + off1;
    const float* p2 = mask + base + off2;
    float*       po = out  + base + off1;

    const unsigned sbase =
        (unsigned)__cvta_generic_to_shared(&sbuf[warp][0][0][lane]);
    // stage stride = 3 rows * 32 lanes * 16B = 1536B; row stride = 512B

    // ---- cp.async prologue: channels 0..2 in flight ----------------------
    {
        CP16(sbase,        p0);
        CP16(sbase + 512,  p1);
        CP16(sbase + 1024, p2);
        CPCOMMIT();
        CP16(sbase + 1536,        p0 + img);
        CP16(sbase + 1536 + 512,  p1 + img);
        CP16(sbase + 1536 + 1024, p2 + img);
        CPCOMMIT();
        CP16(sbase + 3072,        p0 + 2 * img);
        CP16(sbase + 3072 + 512,  p1 + 2 * img);
        CP16(sbase + 3072 + 1024, p2 + 2 * img);
        CPCOMMIT();
    }

    // ---- weights: bilinear-upsampled edge + softmax (overlaps fill) ------
    // e_up(y+dy, x0-1 .. x0+4); zero outside image (reference pads AFTER
    // upsampling). Horizontal neighbors via warp shuffle.
    float w[4][9];
    {
        const float* eptr = edge + n * (EH * EW);
        const float sc = 63.0f / 127.0f;   // (EH-1)/(HH-1), align_corners

        float er[3][6];
        #pragma unroll
        for (int r = 0; r < 3; r++) {
            const int gy = y - 1 + r;
            float4 ev = make_float4(0.f, 0.f, 0.f, 0.f);
            if (gy >= 0 && gy < HH) {
                const float ys = (float)gy * sc;
                const int   yi = (int)ys;
                const float wy = ys - (float)yi;
                const int   y1 = min(yi + 1, EH - 1);
                const float* r0 = eptr + yi * EW;
                const float* r1 = eptr + y1 * EW;
                float v[4];
                #pragma unroll
                for (int p = 0; p < 4; p++) {
                    const int   gx = x0 + p;
                    const float xs = (float)gx * sc;
                    const int   xi = (int)xs;
                    const float wx = xs - (float)xi;
                    const int   x1 = min(xi + 1, EW - 1);
                    const float a  = r0[xi];
                    const float b  = r0[x1];
                    const float c0 = r1[xi];
                    const float d  = r1[x1];
                    const float top = a  + (b  - a ) * wx;
                    const float bot = c0 + (d  - c0) * wx;
                    v[p] = top + (bot - top) * wy;
                }
                ev = make_float4(v[0], v[1], v[2], v[3]);
            }
            float left  = __shfl_up_sync(0xffffffffu, ev.w, 1);
            float right = __shfl_down_sync(0xffffffffu, ev.x, 1);
            if (lane == 0)  left  = 0.f;
            if (lane == 31) right = 0.f;
            er[r][0] = left; er[r][1] = ev.x; er[r][2] = ev.y;
            er[r][3] = ev.z; er[r][4] = ev.w; er[r][5] = right;
        }

        #pragma unroll
        for (int p = 0; p < 4; p++) {
            const float ec = er[1][p + 1];
            float s = 0.f;
            #pragma unroll
            for (int k = 0; k < 9; k++) {
                const float d  = ec - er[k / 3][p + (k % 3)];
                const float pw = __expf(-THETA * d * d);
                w[p][k] = pw;
                s += pw;
            }
            const float rs = 1.f / s;
            #pragma unroll
            for (int k = 0; k < 9; k++) w[p][k] *= rs;
        }

        // Fold mask zero-padding into the (normalized) weights: a padded tap
        // contributes m=0, identical to zeroing its weight; the softmax
        // denominator already includes all 9 exps.
        if (y == 0) {
            #pragma unroll
            for (int p = 0; p < 4; p++) { w[p][0] = 0.f; w[p][1] = 0.f; w[p][2] = 0.f; }
        }
        if (y == HH - 1) {
            #pragma unroll
            for (int p = 0; p < 4; p++) { w[p][6] = 0.f; w[p][7] = 0.f; w[p][8] = 0.f; }
        }
        if (lane == 0)  { w[0][0] = 0.f; w[0][3] = 0.f; w[0][6] = 0.f; }
        if (lane == 31) { w[3][2] = 0.f; w[3][5] = 0.f; w[3][8] = 0.f; }
    }

    // ---- channel loop: FULLY UNROLLED, all offsets immediate --------------
    const float4* stp = &sbuf[warp][0][0][lane];

    #pragma unroll
    for (int c = 0; c < CSPB; c++) {
        // Issue channel c+3 (compile-time predicate). Empty commit groups in
        // the tail keep wait_group accounting sound.
        if (c + 3 < CSPB) {
            const unsigned st = sbase + ((c + 3) & (NSTAGE - 1)) * 1536;
            CP16(st,        p0 + (c + 3) * img);
            CP16(st + 512,  p1 + (c + 3) * img);
            CP16(st + 1024, p2 + (c + 3) * img);
        }
        CPCOMMIT();
        CPWAIT3();          // channel c's group is complete

        const int sidx = (c & (NSTAGE - 1)) * 96;   // float4 units
        float4 m0 = stp[sidx];
        float4 m1 = stp[sidx + 32];
        float4 m2 = stp[sidx + 64];

        float mr[3][6];
        {
            float l0 = __shfl_up_sync(0xffffffffu, m0.w, 1);
            float r0 = __shfl_down_sync(0xffffffffu, m0.x, 1);
            float l1 = __shfl_up_sync(0xffffffffu, m1.w, 1);
            float r1 = __shfl_down_sync(0xffffffffu, m1.x, 1);
            float l2 = __shfl_up_sync(0xffffffffu, m2.w, 1);
            float r2 = __shfl_down_sync(0xffffffffu, m2.x, 1);
            mr[0][0]=l0; mr[0][1]=m0.x; mr[0][2]=m0.y; mr[0][3]=m0.z; mr[0][4]=m0.w; mr[0][5]=r0;
            mr[1][0]=l1; mr[1][1]=m1.x; mr[1][2]=m1.y; mr[1][3]=m1.z; mr[1][4]=m1.w; mr[1][5]=r1;
            mr[2][0]=l2; mr[2][1]=m2.x; mr[2][2]=m2.y; mr[2][3]=m2.z; mr[2][4]=m2.w; mr[2][5]=r2;
        }

        float a[4];
        #pragma unroll
        for (int p = 0; p < 4; p++) {
            float s = 0.f;
            #pragma unroll
            for (int k = 0; k < 9; k++)
                s = fmaf(w[p][k], mr[k / 3][p + (k % 3)], s);
            a[p] = s;
        }

        *reinterpret_cast<float4*>(po + c * img) =
            make_float4(a[0], a[1], a[2], a[3]);
    }
}

extern "C" void kernel_launch(void* const* d_in, const int* in_sizes, int n_in,
                              void* d_out, int out_size)
{
    const float* mask = (const float*)d_in[0];
    const float* edge = (const float*)d_in[1];
    if (n_in >= 2 && in_sizes[0] < in_sizes[1]) {   // defensive swap by size
        const float* tmp = mask; mask = edge; edge = tmp;
    }
    float* out = (float*)d_out;

    dim3 grid(NROWBLK, NCGRP, NB);      // 32 x 4 x 8 = 1024 blocks
    geg_fused_kernel<<<grid, TBLK>>>(mask, edge, out);
}

// round 15
// speedup vs baseline: 1.1358x; 1.0172x over previous
#include <cuda_runtime.h>
#include <cstdint>

// Problem constants (from reference setup_inputs)
#define NB 8
#define NC 64
#define HH 128
#define WW 128
#define EH 64
#define EW 64
#define THETA 10.0f

#define CSPB 16                        // channels per block
#define NCGRP (NC / CSPB)              // 4 channel groups
#define ROWS_PER_BLK 4                 // 4 warps -> 4 rows
#define NROWBLK (HH / ROWS_PER_BLK)    // 32
#define TBLK (ROWS_PER_BLK * 32)       // 128 threads
#define NSTAGE 4                       // cp.async ring depth (3 ahead)

#define CP16(dst, src) \
    asm volatile("cp.async.cg.shared.global [%0], [%1], 16;" \
                 :: "r"(dst), "l"(src) : "memory")
#define CPCOMMIT() asm volatile("cp.async.commit_group;" ::: "memory")
#define CPWAIT3()  asm volatile("cp.async.wait_group 3;"  ::: "memory")

// Packed fp32x2 ops (sm_103a): one fma-pipe instruction, two fp32 lanes.
__device__ __forceinline__ uint64_t pk(float lo, float hi) {
    uint64_t r;
    asm("mov.b64 %0, {%1, %2};" : "=l"(r) : "f"(lo), "f"(hi));
    return r;
}
__device__ __forceinline__ uint64_t fma2(uint64_t a, uint64_t b, uint64_t c) {
    uint64_t d;
    asm("fma.rn.f32x2 %0, %1, %2, %3;" : "=l"(d) : "l"(a), "l"(b), "l"(c));
    return d;
}
__device__ __forceinline__ void upk(float& lo, float& hi, uint64_t v) {
    asm("mov.b64 {%0, %1}, %2;" : "=f"(lo), "=f"(hi) : "l"(v));
}

// ---------------------------------------------------------------------------
// Fused kernel (R14 structure): per-block weight computation (bilinear edge
// upsample + softmax, boundary padding folded into weights) followed by a
// FULLY UNROLLED 16-channel apply loop fed by a warp-private cp.async
// pipeline (3 channels ahead, per-warp commit/wait, no block barriers).
// NEW: the 9-tap apply uses packed fma.rn.f32x2 — 18 FFMA2 instead of 36
// scalar FFMA per iteration (exact fp32 numerics per lane).
// ---------------------------------------------------------------------------
__global__ __launch_bounds__(TBLK, 7)
void geg_fused_kernel(const float* __restrict__ mask,
                      const float* __restrict__ edge,
                      float* __restrict__ out)
{
    // [warp][stage][row][lane] float4 = 24 KB
    __shared__ float4 sbuf[ROWS_PER_BLK][NSTAGE][3][32];

    const int t    = threadIdx.x;
    const int warp = t >> 5;
    const int lane = t & 31;

    const int rowblk = blockIdx.x;     // 0..31
    const int cgrp   = blockIdx.y;     // 0..3
    const int n      = blockIdx.z;     // 0..7

    const int y  = rowblk * ROWS_PER_BLK + warp;  // output row, 0..127
    const int x0 = lane * 4;

    const int img  = HH * WW;
    const int base = (n * NC + cgrp * CSPB) * img;

    // Clamped row offsets (OOB rows carry zero weight).
    const int off0 = max(y - 1, 0)      * WW + x0;
    const int off1 = y                  * WW + x0;
    const int off2 = min(y + 1, HH - 1) * WW + x0;

    const float* p0 = mask + base + off0;
    const float* p1 = mask + base + off1;
    const float* p2 = mask + base + off2;
    float*       po = out  + base + off1;

    const unsigned sbase =
        (unsigned)__cvta_generic_to_shared(&sbuf[warp][0][0][lane]);
    // stage stride = 1536B; row stride = 512B

    // ---- cp.async prologue: channels 0..2 in flight ----------------------
    {
        CP16(sbase,        p0);
        CP16(sbase + 512,  p1);
        CP16(sbase + 1024, p2);
        CPCOMMIT();
        CP16(sbase + 1536,        p0 + img);
        CP16(sbase + 1536 + 512,  p1 + img);
        CP16(sbase + 1536 + 1024, p2 + img);
        CPCOMMIT();
        CP16(sbase + 3072,        p0 + 2 * img);
        CP16(sbase + 3072 + 512,  p1 + 2 * img);
        CP16(sbase + 3072 + 1024, p2 + 2 * img);
        CPCOMMIT();
    }

    // ---- weights: bilinear-upsampled edge + softmax (overlaps fill) ------
    float w[4][9];
    {
        const float* eptr = edge + n * (EH * EW);
        const float sc = 63.0f / 127.0f;   // (EH-1)/(HH-1), align_corners

        float er[3][6];
        #pragma unroll
        for (int r = 0; r < 3; r++) {
            const int gy = y - 1 + r;
            float4 ev = make_float4(0.f, 0.f, 0.f, 0.f);
            if (gy >= 0 && gy < HH) {
                const float ys = (float)gy * sc;
                const int   yi = (int)ys;
                const float wy = ys - (float)yi;
                const int   y1 = min(yi + 1, EH - 1);
                const float* r0 = eptr + yi * EW;
                const float* r1 = eptr + y1 * EW;
                float v[4];
                #pragma unroll
                for (int p = 0; p < 4; p++) {
                    const int   gx = x0 + p;
                    const float xs = (float)gx * sc;
                    const int   xi = (int)xs;
                    const float wx = xs - (float)xi;
                    const int   x1 = min(xi + 1, EW - 1);
                    const float a  = r0[xi];
                    const float b  = r0[x1];
                    const float c0 = r1[xi];
                    const float d  = r1[x1];
                    const float top = a  + (b  - a ) * wx;
                    const float bot = c0 + (d  - c0) * wx;
                    v[p] = top + (bot - top) * wy;
                }
                ev = make_float4(v[0], v[1], v[2], v[3]);
            }
            float left  = __shfl_up_sync(0xffffffffu, ev.w, 1);
            float right = __shfl_down_sync(0xffffffffu, ev.x, 1);
            if (lane == 0)  left  = 0.f;
            if (lane == 31) right = 0.f;
            er[r][0] = left; er[r][1] = ev.x; er[r][2] = ev.y;
            er[r][3] = ev.z; er[r][4] = ev.w; er[r][5] = right;
        }

        #pragma unroll
        for (int p = 0; p < 4; p++) {
            const float ec = er[1][p + 1];
            float s = 0.f;
            #pragma unroll
            for (int k = 0; k < 9; k++) {
                const float d  = ec - er[k / 3][p + (k % 3)];
                const float pw = __expf(-THETA * d * d);
                w[p][k] = pw;
                s += pw;
            }
            const float rs = 1.f / s;
            #pragma unroll
            for (int k = 0; k < 9; k++) w[p][k] *= rs;
        }

        // Fold mask zero-padding into the (normalized) weights.
        if (y == 0) {
            #pragma unroll
            for (int p = 0; p < 4; p++) { w[p][0] = 0.f; w[p][1] = 0.f; w[p][2] = 0.f; }
        }
        if (y == HH - 1) {
            #pragma unroll
            for (int p = 0; p < 4; p++) { w[p][6] = 0.f; w[p][7] = 0.f; w[p][8] = 0.f; }
        }
        if (lane == 0)  { w[0][0] = 0.f; w[0][3] = 0.f; w[0][6] = 0.f; }
        if (lane == 31) { w[3][2] = 0.f; w[3][5] = 0.f; w[3][8] = 0.f; }
    }

    // Pack weights for pixel pairs (0,1) and (2,3): 18 x 64-bit registers.
    uint64_t w01[9], w23[9];
    #pragma unroll
    for (int k = 0; k < 9; k++) {
        w01[k] = pk(w[0][k], w[1][k]);
        w23[k] = pk(w[2][k], w[3][k]);
    }

    // ---- channel loop: FULLY UNROLLED, packed f32x2 FMAs ------------------
    const float4* stp = &sbuf[warp][0][0][lane];
    const uint64_t z = 0;   // packed (0,0)

    #pragma unroll
    for (int c = 0; c < CSPB; c++) {
        if (c + 3 < CSPB) {
            const unsigned st = sbase + ((c + 3) & (NSTAGE - 1)) * 1536;
            CP16(st,        p0 + (c + 3) * img);
            CP16(st + 512,  p1 + (c + 3) * img);
            CP16(st + 1024, p2 + (c + 3) * img);
        }
        CPCOMMIT();
        CPWAIT3();          // channel c's group is complete

        const int sidx = (c & (NSTAGE - 1)) * 96;   // float4 units
        float4 m0 = stp[sidx];
        float4 m1 = stp[sidx + 32];
        float4 m2 = stp[sidx + 64];

        float l0 = __shfl_up_sync(0xffffffffu, m0.w, 1);
        float r0 = __shfl_down_sync(0xffffffffu, m0.x, 1);
        float l1 = __shfl_up_sync(0xffffffffu, m1.w, 1);
        float r1 = __shfl_down_sync(0xffffffffu, m1.x, 1);
        float l2 = __shfl_up_sync(0xffffffffu, m2.w, 1);
        float r2 = __shfl_down_sync(0xffffffffu, m2.x, 1);

        // Sliding 64-bit pairs per row: P0=(l,x) P1=(x,y) P2=(y,z) P3=(z,w)
        // P4=(w,r). P1/P3 are free (LDS.128 quad is reg-pair aligned).
        uint64_t acc01 = z, acc23 = z;
        {   // row 0, taps k=0..2
            uint64_t q0 = pk(l0,   m0.x), q1 = pk(m0.x, m0.y);
            uint64_t q2 = pk(m0.y, m0.z), q3 = pk(m0.z, m0.w);
            uint64_t q4 = pk(m0.w, r0);
            acc01 = fma2(w01[0], q0, acc01);  acc23 = fma2(w23[0], q2, acc23);
            acc01 = fma2(w01[1], q1, acc01);  acc23 = fma2(w23[1], q3, acc23);
            acc01 = fma2(w01[2], q2, acc01);  acc23 = fma2(w23[2], q4, acc23);
        }
        {   // row 1, taps k=3..5
            uint64_t q0 = pk(l1,   m1.x), q1 = pk(m1.x, m1.y);
            uint64_t q2 = pk(m1.y, m1.z), q3 = pk(m1.z, m1.w);
            uint64_t q4 = pk(m1.w, r1);
            acc01 = fma2(w01[3], q0, acc01);  acc23 = fma2(w23[3], q2, acc23);
            acc01 = fma2(w01[4], q1, acc01);  acc23 = fma2(w23[4], q3, acc23);
            acc01 = fma2(w01[5], q2, acc01);  acc23 = fma2(w23[5], q4, acc23);
        }
        {   // row 2, taps k=6..8
            uint64_t q0 = pk(l2,   m2.x), q1 = pk(m2.x, m2.y);
            uint64_t q2 = pk(m2.y, m2.z), q3 = pk(m2.z, m2.w);
            uint64_t q4 = pk(m2.w, r2);
            acc01 = fma2(w01[6], q0, acc01);  acc23 = fma2(w23[6], q2, acc23);
            acc01 = fma2(w01[7], q1, acc01);  acc23 = fma2(w23[7], q3, acc23);
            acc01 = fma2(w01[8], q2, acc01);  acc23 = fma2(w23[8], q4, acc23);
        }

        float a0, a1, a2, a3;
        upk(a0, a1, acc01);
        upk(a2, a3, acc23);

        *reinterpret_cast<float4*>(po + c * img) = make_float4(a0, a1, a2, a3);
    }
}

extern "C" void kernel_launch(void* const* d_in, const int* in_sizes, int n_in,
                              void* d_out, int out_size)
{
    const float* mask = (const float*)d_in[0];
    const float* edge = (const float*)d_in[1];
    if (n_in >= 2 && in_sizes[0] < in_sizes[1]) {   // defensive swap by size
        const float* tmp = mask; mask = edge; edge = tmp;
    }
    float* out = (float*)d_out;

    dim3 grid(NROWBLK, NCGRP, NB);      // 32 x 4 x 8 = 1024 blocks
    geg_fused_kernel<<<grid, TBLK>>>(mask, edge, out);
}